// round 1
// baseline (speedup 1.0000x reference)
#include <cuda_runtime.h>
#include <cstdint>

// Haar DWT2: in [B=8, C=32, H=512, W=512] f32 -> out [B, 4, C, 256, 256] f32
// Subband order: LL, LH, HL, HH (pywt dwt2 'haar' convention per reference).
//
// Each thread: reads 2 rows x 4 cols (two float4 loads), writes float2 to each
// of the 4 subbands. All accesses fully coalesced.

#define B_  8
#define C_  32
#define H_  512
#define W_  512
#define H2 (H_/2)
#define W2 (W_/2)

__global__ void __launch_bounds__(256) haar_dwt2_kernel(
    const float* __restrict__ in, float* __restrict__ out)
{
    // total threads = B*C*H2*(W2/2) = 8*32*256*128
    const int64_t tid = (int64_t)blockIdx.x * blockDim.x + threadIdx.x;

    const int wpair = (int)(tid & (W2/2 - 1));          // 0..127  (2 output cols each)
    const int h2    = (int)((tid >> 7) & (H2 - 1));     // 0..255
    const int bc    = (int)(tid >> 15);                 // 0..255  (b*32 + c)
    const int b     = bc >> 5;
    const int c     = bc & 31;

    // Input: rows 2*h2 and 2*h2+1, cols 4*wpair .. 4*wpair+3
    const int64_t in_row0 = ((int64_t)bc * H_ + 2 * h2) * W_ + 4 * wpair;
    const float4 r0 = *reinterpret_cast<const float4*>(in + in_row0);
    const float4 r1 = *reinterpret_cast<const float4*>(in + in_row0 + W_);

    // pairs: (r.x,r.y) -> output col 2*wpair ; (r.z,r.w) -> 2*wpair+1
    // x00=r0.x x01=r0.y x10=r1.x x11=r1.y  (first pair), same with z/w.
    float2 LL, LH, HL, HH;
    LL.x = (r0.x + r0.y + r1.x + r1.y) * 0.5f;
    LH.x = (r0.x + r0.y - r1.x - r1.y) * 0.5f;
    HL.x = (r0.x - r0.y + r1.x - r1.y) * 0.5f;
    HH.x = (r0.x - r0.y - r1.x + r1.y) * 0.5f;
    LL.y = (r0.z + r0.w + r1.z + r1.w) * 0.5f;
    LH.y = (r0.z + r0.w - r1.z - r1.w) * 0.5f;
    HL.y = (r0.z - r0.w + r1.z - r1.w) * 0.5f;
    HH.y = (r0.z - r0.w - r1.z + r1.w) * 0.5f;

    // Output: [B, 4, C, H2, W2]
    const int64_t plane = (int64_t)H2 * W2;                       // 65536
    const int64_t obase = (((int64_t)b * 4) * C_ + c) * plane
                          + (int64_t)h2 * W2 + 2 * wpair;
    const int64_t sstride = (int64_t)C_ * plane;                  // subband stride

    *reinterpret_cast<float2*>(out + obase)               = LL;
    *reinterpret_cast<float2*>(out + obase + sstride)     = LH;
    *reinterpret_cast<float2*>(out + obase + 2 * sstride) = HL;
    *reinterpret_cast<float2*>(out + obase + 3 * sstride) = HH;
}

extern "C" void kernel_launch(void* const* d_in, const int* in_sizes, int n_in,
                              void* d_out, int out_size)
{
    const float* in = (const float*)d_in[0];
    float* out = (float*)d_out;

    const int64_t total_threads = (int64_t)B_ * C_ * H2 * (W2 / 2);   // 8,388,608
    const int threads = 256;
    const int blocks = (int)(total_threads / threads);                 // 32,768

    haar_dwt2_kernel<<<blocks, threads>>>(in, out);
}